// round 4
// baseline (speedup 1.0000x reference)
#include <cuda_runtime.h>

#define NN 100000
#define NE 1600000
#define NG 512
#define F  128
#define NCONV 4

typedef unsigned long long ull;
typedef unsigned int uint;

// ---------------- scratch (device globals; no allocation) ----------------
__device__ uint  g_bufA[NN * (F / 2)];   // g = (x@W)*dinv[row], packed bf16x2 (25.6MB)
__device__ float g_bufB[NN * F];         // x_next fp32
__device__ int   g_cnt[NN];
__device__ int   g_rowptr[NN + 1];
__device__ int   g_cursor[NN];
__device__ int   g_csr[NE];
__device__ int   g_blksum[128];
__device__ int   g_blkoff[128];
__device__ float g_dinv[NN];
__device__ float g_gsum[NG * F];
__device__ float g_gcnt[NG];

// ---------------- utility ----------------
__global__ void fill_zero(float* __restrict__ p, int n4) {
    int i = blockIdx.x * blockDim.x + threadIdx.x;
    if (i < n4) reinterpret_cast<float4*>(p)[i] = make_float4(0.f, 0.f, 0.f, 0.f);
}

__global__ void count_kernel(const int* __restrict__ ei, int* __restrict__ cnt) {
    int e = blockIdx.x * blockDim.x + threadIdx.x;
    if (e < NE) atomicAdd(&cnt[ei[NE + e]], 1);
}

// ---------------- CSR build: scan over counts (dinv fused into scan1) ----------------
__global__ void scan1(const int* __restrict__ cnt, int* __restrict__ rowptr,
                      int* __restrict__ blksum, float* __restrict__ dinv) {
    __shared__ int s[1024];
    int i = blockIdx.x * 1024 + threadIdx.x;
    int v = (i < NN) ? cnt[i] : 0;
    if (i < NN) dinv[i] = rsqrtf((float)v + 2.0f);   // improved=True self-loop weight 2
    s[threadIdx.x] = v;
    __syncthreads();
    #pragma unroll
    for (int off = 1; off < 1024; off <<= 1) {
        int t = (threadIdx.x >= off) ? s[threadIdx.x - off] : 0;
        __syncthreads();
        s[threadIdx.x] += t;
        __syncthreads();
    }
    if (i < NN) rowptr[i + 1] = s[threadIdx.x];
    if (threadIdx.x == 1023) blksum[blockIdx.x] = s[1023];
    if (i == 0) rowptr[0] = 0;
}

__global__ void scan2(const int* __restrict__ blksum, int* __restrict__ blkoff, int nb) {
    __shared__ int s[128];
    int t = threadIdx.x;
    s[t] = (t < nb) ? blksum[t] : 0;
    __syncthreads();
    #pragma unroll
    for (int off = 1; off < 128; off <<= 1) {
        int v = (t >= off) ? s[t - off] : 0;
        __syncthreads();
        s[t] += v;
        __syncthreads();
    }
    if (t < nb) blkoff[t] = (t == 0) ? 0 : s[t - 1];
}

__global__ void scan3(int* __restrict__ rowptr, const int* __restrict__ blkoff,
                      int* __restrict__ cursor) {
    int j = blockIdx.x * blockDim.x + threadIdx.x + 1;   // 1..NN
    if (j <= NN) {
        int v = rowptr[j] + blkoff[(j - 1) >> 10];
        rowptr[j] = v;
        if (j < NN) cursor[j] = v;
    }
    if (j == 1) cursor[0] = 0;
}

__global__ void csr_fill(const int* __restrict__ ei, int* __restrict__ cursor,
                         int* __restrict__ csr) {
    int e = blockIdx.x * blockDim.x + threadIdx.x;
    if (e >= NE) return;
    int dst = ei[NE + e];
    int pos = atomicAdd(&cursor[dst], 1);
    csr[pos] = ei[e];
}

// ---------------- packed bf16 helpers ----------------
__device__ __forceinline__ uint pk_bf16x2(float lo, float hi) {
    uint r;
    asm("cvt.rn.bf16x2.f32 %0, %1, %2;" : "=r"(r) : "f"(hi), "f"(lo));
    return r;
}

// ---------------- scaled GEMM (f32x2 packed), bf16 packed output ----------------
// out_bf[r][c] = bf16( dinv[r] * sum_k X[r][k] * W[k][c] )
#define GEMM_SMEM ((F * F) * 4 + (32 * F) * 8)   // 98304 bytes

__device__ __forceinline__ void ffma2(ull& d, ull a, ull b) {
    asm("fma.rn.f32x2 %0, %1, %2, %0;" : "+l"(d) : "l"(a), "l"(b));
}
__device__ __forceinline__ void unpk2(ull p, float& lo, float& hi) {
    asm("mov.b64 {%0, %1}, %2;" : "=f"(lo), "=f"(hi) : "l"(p));
}

__global__ void gemm_scaled(const float* __restrict__ X, const float* __restrict__ W,
                            const float* __restrict__ dinv, uint* __restrict__ out) {
    extern __shared__ float sm[];
    float* ws = sm;                            // [128][128] floats
    ull* xsd = (ull*)(sm + F * F);             // [32][128] duplicated pairs
    const int t = threadIdx.x;
    const int row0 = blockIdx.x * 32;

    const float4* W4 = reinterpret_cast<const float4*>(W);
    float4* ws4 = reinterpret_cast<float4*>(ws);
    #pragma unroll
    for (int i = t; i < (F * F) / 4; i += 256) ws4[i] = W4[i];

    const float4* X4 = reinterpret_cast<const float4*>(X + (size_t)row0 * F);
    #pragma unroll
    for (int i = t; i < (32 * F) / 4; i += 256) {
        float4 v = X4[i];
        ull p0, p1, p2, p3;
        asm("mov.b64 %0, {%1, %1};" : "=l"(p0) : "f"(v.x));
        asm("mov.b64 %0, {%1, %1};" : "=l"(p1) : "f"(v.y));
        asm("mov.b64 %0, {%1, %1};" : "=l"(p2) : "f"(v.z));
        asm("mov.b64 %0, {%1, %1};" : "=l"(p3) : "f"(v.w));
        xsd[i * 4 + 0] = p0; xsd[i * 4 + 1] = p1;
        xsd[i * 4 + 2] = p2; xsd[i * 4 + 3] = p3;
    }
    __syncthreads();

    const int c4 = t & 31;        // which group of 4 output cols
    const int w  = t >> 5;        // warp id 0..7 -> rows 4w..4w+3
    const int r  = w * 4;
    const ull* xp = xsd + r * F;
    const ulonglong2* wsu = reinterpret_cast<const ulonglong2*>(ws);

    ull a00 = 0, a01 = 0, a10 = 0, a11 = 0, a20 = 0, a21 = 0, a30 = 0, a31 = 0;

    #pragma unroll 8
    for (int k = 0; k < F; k++) {
        ulonglong2 wv = wsu[k * 32 + c4];
        ull x0 = xp[k];
        ull x1 = xp[F + k];
        ull x2 = xp[2 * F + k];
        ull x3 = xp[3 * F + k];
        ffma2(a00, x0, wv.x); ffma2(a01, x0, wv.y);
        ffma2(a10, x1, wv.x); ffma2(a11, x1, wv.y);
        ffma2(a20, x2, wv.x); ffma2(a21, x2, wv.y);
        ffma2(a30, x3, wv.x); ffma2(a31, x3, wv.y);
    }

    uint2* O2 = reinterpret_cast<uint2*>(out);
    float d0 = dinv[row0 + r + 0];
    float d1 = dinv[row0 + r + 1];
    float d2 = dinv[row0 + r + 2];
    float d3 = dinv[row0 + r + 3];
    float4 o;
    unpk2(a00, o.x, o.y); unpk2(a01, o.z, o.w);
    O2[(size_t)(row0 + r + 0) * 32 + c4] =
        make_uint2(pk_bf16x2(o.x * d0, o.y * d0), pk_bf16x2(o.z * d0, o.w * d0));
    unpk2(a10, o.x, o.y); unpk2(a11, o.z, o.w);
    O2[(size_t)(row0 + r + 1) * 32 + c4] =
        make_uint2(pk_bf16x2(o.x * d1, o.y * d1), pk_bf16x2(o.z * d1, o.w * d1));
    unpk2(a20, o.x, o.y); unpk2(a21, o.z, o.w);
    O2[(size_t)(row0 + r + 2) * 32 + c4] =
        make_uint2(pk_bf16x2(o.x * d2, o.y * d2), pk_bf16x2(o.z * d2, o.w * d2));
    unpk2(a30, o.x, o.y); unpk2(a31, o.z, o.w);
    O2[(size_t)(row0 + r + 3) * 32 + c4] =
        make_uint2(pk_bf16x2(o.x * d3, o.y * d3), pk_bf16x2(o.z * d3, o.w * d3));
}

// ---------------- gather + combine: half-warp per edge, LDG.128 ----------------
// x_next[n] = relu( dinv[n] * (sum_{e in in(n)} g[src_e] + 2*g[n]) + b )
// Lane layout: half = lane>>4 (edge parity within a pair), hl = lane&15.
// Each lane loads uint4 = 8 bf16 feats [hl*8, hl*8+8); halves merged via shfl_xor(16).
#define ACC8(v)                                              \
    acc[0] += __uint_as_float((v).x << 16);                  \
    acc[1] += __uint_as_float((v).x & 0xffff0000u);          \
    acc[2] += __uint_as_float((v).y << 16);                  \
    acc[3] += __uint_as_float((v).y & 0xffff0000u);          \
    acc[4] += __uint_as_float((v).z << 16);                  \
    acc[5] += __uint_as_float((v).z & 0xffff0000u);          \
    acc[6] += __uint_as_float((v).w << 16);                  \
    acc[7] += __uint_as_float((v).w & 0xffff0000u);

__global__ void gather_combine(const int* __restrict__ rowptr, const int* __restrict__ csr,
                               const uint* __restrict__ g, const float* __restrict__ dinv,
                               const float* __restrict__ bias, float* __restrict__ out) {
    int n = (blockIdx.x * blockDim.x + threadIdx.x) >> 5;
    if (n >= NN) return;
    int lane = threadIdx.x & 31;
    int half = lane >> 4;
    int hl   = lane & 15;
    int start = rowptr[n];
    int end   = rowptr[n + 1];

    const uint4* g4 = reinterpret_cast<const uint4*>(g);   // 16 uint4 per node row

    float acc[8];
    #pragma unroll
    for (int i = 0; i < 8; i++) acc[i] = 0.f;

    for (int base = start; base < end; base += 32) {
        int m = min(32, end - base);
        int s = (lane < m) ? csr[base + lane] : 0;
        int mp = m & ~1;
        #pragma unroll 4
        for (int j = 0; j < mp; j += 2) {
            int src = __shfl_sync(0xffffffffu, s, j + half);
            uint4 v = g4[(size_t)src * 16 + hl];
            ACC8(v)
        }
        if (m & 1) {
            int src = __shfl_sync(0xffffffffu, s, m - 1);
            if (half == 0) {
                uint4 v = g4[(size_t)src * 16 + hl];
                ACC8(v)
            }
        }
    }

    // merge the two halves (feature layout is identical in both)
    #pragma unroll
    for (int i = 0; i < 8; i++)
        acc[i] += __shfl_xor_sync(0xffffffffu, acc[i], 16);

    if (half == 0) {
        float dv = dinv[n];
        uint4 sv = g4[(size_t)n * 16 + hl];
        float s0 = __uint_as_float(sv.x << 16),       s1 = __uint_as_float(sv.x & 0xffff0000u);
        float s2 = __uint_as_float(sv.y << 16),       s3 = __uint_as_float(sv.y & 0xffff0000u);
        float s4 = __uint_as_float(sv.z << 16),       s5 = __uint_as_float(sv.z & 0xffff0000u);
        float s6 = __uint_as_float(sv.w << 16),       s7 = __uint_as_float(sv.w & 0xffff0000u);
        const float4* b4 = reinterpret_cast<const float4*>(bias);
        float4 b0 = b4[hl * 2], b1 = b4[hl * 2 + 1];
        float4 r0, r1;
        r0.x = fmaxf(dv * (acc[0] + 2.f * s0) + b0.x, 0.f);
        r0.y = fmaxf(dv * (acc[1] + 2.f * s1) + b0.y, 0.f);
        r0.z = fmaxf(dv * (acc[2] + 2.f * s2) + b0.z, 0.f);
        r0.w = fmaxf(dv * (acc[3] + 2.f * s3) + b0.w, 0.f);
        r1.x = fmaxf(dv * (acc[4] + 2.f * s4) + b1.x, 0.f);
        r1.y = fmaxf(dv * (acc[5] + 2.f * s5) + b1.y, 0.f);
        r1.z = fmaxf(dv * (acc[6] + 2.f * s6) + b1.z, 0.f);
        r1.w = fmaxf(dv * (acc[7] + 2.f * s7) + b1.w, 0.f);
        float4* o4 = reinterpret_cast<float4*>(out) + (size_t)n * 32 + hl * 2;
        o4[0] = r0;
        o4[1] = r1;
    }
}

// ---------------- pooling: run-length accumulate over sorted batch ----------------
__global__ void pool_kernel(const float* __restrict__ x, const int* __restrict__ batch,
                            float* __restrict__ gsum) {
    int f  = threadIdx.x;            // 128
    int n0 = blockIdx.x * 64;
    if (n0 >= NN) return;
    int nend = min(n0 + 64, NN);
    int cur = batch[n0];
    float acc = 0.f;
    for (int n = n0; n < nend; n++) {
        int b = batch[n];
        if (b != cur) { atomicAdd(&gsum[cur * F + f], acc); acc = 0.f; cur = b; }
        acc += x[(size_t)n * F + f];
    }
    atomicAdd(&gsum[cur * F + f], acc);
}

__global__ void cnt_kernel(const int* __restrict__ batch, float* __restrict__ gcnt) {
    int n = blockIdx.x * blockDim.x + threadIdx.x;
    if (n < NN) atomicAdd(&gcnt[batch[n]], 1.0f);
}

// ---------------- MLP head: one block per graph ----------------
__global__ void head_kernel(const float* __restrict__ gsum, const float* __restrict__ gcnt,
                            const float* __restrict__ fc1w, const float* __restrict__ fc1b,
                            const float* __restrict__ fc2w, const float* __restrict__ fc2b,
                            float* __restrict__ out) {
    int gI = blockIdx.x;
    int f  = threadIdx.x;            // 128
    __shared__ float pooled[F];
    __shared__ float red[F];
    float cnt = fmaxf(gcnt[gI], 1.0f);
    pooled[f] = gsum[gI * F + f] / cnt;
    __syncthreads();
    float a = fc1b[f];
    #pragma unroll 8
    for (int k = 0; k < F; k++) a += pooled[k] * fc1w[k * F + f];
    red[f] = fmaxf(a, 0.f) * fc2w[f];
    __syncthreads();
    #pragma unroll
    for (int s = 64; s > 0; s >>= 1) {
        if (f < s) red[f] += red[f + s];
        __syncthreads();
    }
    if (f == 0) out[gI] = red[0] + fc2b[0];
}

// ---------------- launch ----------------
extern "C" void kernel_launch(void* const* d_in, const int* in_sizes, int n_in,
                              void* d_out, int out_size) {
    const float* x      = (const float*)d_in[0];
    const int*   ei     = (const int*)d_in[1];
    const int*   batch  = (const int*)d_in[2];
    const float* conv_w = (const float*)d_in[4];
    const float* conv_b = (const float*)d_in[5];
    const float* fc1w   = (const float*)d_in[6];
    const float* fc1b   = (const float*)d_in[7];
    const float* fc2w   = (const float*)d_in[8];
    const float* fc2b   = (const float*)d_in[9];
    float* out = (float*)d_out;

    float *bufB, *dinv, *gsum, *gcnt;
    uint *bufA;
    int *cnt, *rowptr, *cursor, *csr, *blksum, *blkoff;
    cudaGetSymbolAddress((void**)&bufA,   g_bufA);
    cudaGetSymbolAddress((void**)&bufB,   g_bufB);
    cudaGetSymbolAddress((void**)&cnt,    g_cnt);
    cudaGetSymbolAddress((void**)&rowptr, g_rowptr);
    cudaGetSymbolAddress((void**)&cursor, g_cursor);
    cudaGetSymbolAddress((void**)&csr,    g_csr);
    cudaGetSymbolAddress((void**)&blksum, g_blksum);
    cudaGetSymbolAddress((void**)&blkoff, g_blkoff);
    cudaGetSymbolAddress((void**)&dinv,   g_dinv);
    cudaGetSymbolAddress((void**)&gsum,   g_gsum);
    cudaGetSymbolAddress((void**)&gcnt,   g_gcnt);

    cudaFuncSetAttribute(gemm_scaled, cudaFuncAttributeMaxDynamicSharedMemorySize, GEMM_SMEM);

    const int NB_SCAN = (NN + 1023) / 1024;   // 98

    // CSR build; gemm L0 placed at absolute launch #4 (the slot ncu captures).
    // gemm L0 only depends on dinv (scan1), not on the CSR.
    fill_zero<<<(NN / 4 + 255) / 256, 256>>>((float*)cnt, NN / 4);            // 1
    count_kernel<<<(NE + 255) / 256, 256>>>(ei, cnt);                         // 2
    scan1<<<NB_SCAN, 1024>>>(cnt, rowptr, blksum, dinv);                      // 3
    gemm_scaled<<<NN / 32, 256, GEMM_SMEM>>>(x, conv_w, dinv, bufA);          // 4 (profiled)
    scan2<<<1, 128>>>(blksum, blkoff, NB_SCAN);                               // 5
    scan3<<<(NN + 255) / 256, 256>>>(rowptr, blkoff, cursor);                 // 6
    csr_fill<<<(NE + 255) / 256, 256>>>(ei, cursor, csr);                     // 7
    gather_combine<<<(NN * 32 + 255) / 256, 256>>>(rowptr, csr, bufA, dinv, conv_b, bufB); // 8

    const float* X = bufB;
    for (int l = 1; l < NCONV; l++) {
        gemm_scaled<<<NN / 32, 256, GEMM_SMEM>>>(X, conv_w + (size_t)l * F * F, dinv, bufA);
        gather_combine<<<(NN * 32 + 255) / 256, 256>>>(rowptr, csr, bufA, dinv,
                                                       conv_b + (size_t)l * F, bufB);
        X = bufB;
    }

    // global mean pool
    fill_zero<<<(NG * F / 4 + 255) / 256, 256>>>(gsum, NG * F / 4);
    fill_zero<<<1, 128>>>(gcnt, NG / 4);
    pool_kernel<<<(NN + 63) / 64, 128>>>(bufB, batch, gsum);
    cnt_kernel<<<(NN + 255) / 256, 256>>>(batch, gcnt);

    // head
    head_kernel<<<NG, 128>>>(gsum, gcnt, fc1w, fc1b, fc2w, fc2b, out);
}

// round 6
// speedup vs baseline: 2.0512x; 2.0512x over previous
#include <cuda_runtime.h>
#include <cuda_bf16.h>

#define NN 100000
#define NE 1600000
#define NG 512
#define F  128
#define NCONV 4

typedef unsigned int uint;

// ---------------- scratch (device globals; no allocation) ----------------
__device__ uint  g_xb[NN * (F / 2)];     // layer input x, packed bf16x2 (25.6MB)
__device__ uint  g_bufA[NN * (F / 2)];   // g = (x@W)*dinv[row], packed bf16x2
__device__ __nv_bfloat16 g_wtb[NCONV * F * F];  // W^T per layer, [l][c][k] bf16
__device__ int   g_cnt[NN];
__device__ int   g_rowptr[NN + 1];
__device__ int   g_cursor[NN];
__device__ int   g_csr[NE];
__device__ int   g_blksum[128];
__device__ int   g_blkoff[128];
__device__ float g_dinv[NN];
__device__ float g_gsum[NG * F];
__device__ float g_gcnt[NG];

// ---------------- utility ----------------
__global__ void fill_zero(float* __restrict__ p, int n4) {
    int i = blockIdx.x * blockDim.x + threadIdx.x;
    if (i < n4) reinterpret_cast<float4*>(p)[i] = make_float4(0.f, 0.f, 0.f, 0.f);
}

__global__ void count_kernel(const int* __restrict__ ei, int* __restrict__ cnt) {
    int e = blockIdx.x * blockDim.x + threadIdx.x;
    if (e < NE) atomicAdd(&cnt[ei[NE + e]], 1);
}

__device__ __forceinline__ uint pk_bf16x2(float lo, float hi) {
    uint r;
    asm("cvt.rn.bf16x2.f32 %0, %1, %2;" : "=r"(r) : "f"(hi), "f"(lo));
    return r;
}

// convert x0 -> packed bf16, and W -> W^T bf16, in one launch
__global__ void convert_all(const float* __restrict__ x, const float* __restrict__ W,
                            uint* __restrict__ xb, __nv_bfloat16* __restrict__ wtb) {
    int i = blockIdx.x * blockDim.x + threadIdx.x;
    if (i < NN * (F / 2)) {
        float2 v = reinterpret_cast<const float2*>(x)[i];
        xb[i] = pk_bf16x2(v.x, v.y);
    } else {
        int j = i - NN * (F / 2);
        if (j < NCONV * F * F) {
            int l = j >> 14, r = j & 16383, c = r >> 7, k = r & 127;
            wtb[j] = __float2bfloat16(W[(l << 14) + (k << 7) + c]);
        }
    }
}

// ---------------- CSR build ----------------
__global__ void scan1(const int* __restrict__ cnt, int* __restrict__ rowptr,
                      int* __restrict__ blksum, float* __restrict__ dinv) {
    __shared__ int s[1024];
    int i = blockIdx.x * 1024 + threadIdx.x;
    int v = (i < NN) ? cnt[i] : 0;
    if (i < NN) dinv[i] = rsqrtf((float)v + 2.0f);
    s[threadIdx.x] = v;
    __syncthreads();
    #pragma unroll
    for (int off = 1; off < 1024; off <<= 1) {
        int t = (threadIdx.x >= off) ? s[threadIdx.x - off] : 0;
        __syncthreads();
        s[threadIdx.x] += t;
        __syncthreads();
    }
    if (i < NN) rowptr[i + 1] = s[threadIdx.x];
    if (threadIdx.x == 1023) blksum[blockIdx.x] = s[1023];
    if (i == 0) rowptr[0] = 0;
}

__global__ void scan2(const int* __restrict__ blksum, int* __restrict__ blkoff, int nb) {
    __shared__ int s[128];
    int t = threadIdx.x;
    s[t] = (t < nb) ? blksum[t] : 0;
    __syncthreads();
    #pragma unroll
    for (int off = 1; off < 128; off <<= 1) {
        int v = (t >= off) ? s[t - off] : 0;
        __syncthreads();
        s[t] += v;
        __syncthreads();
    }
    if (t < nb) blkoff[t] = (t == 0) ? 0 : s[t - 1];
}

__global__ void scan3(int* __restrict__ rowptr, const int* __restrict__ blkoff,
                      int* __restrict__ cursor) {
    int j = blockIdx.x * blockDim.x + threadIdx.x + 1;
    if (j <= NN) {
        int v = rowptr[j] + blkoff[(j - 1) >> 10];
        rowptr[j] = v;
        if (j < NN) cursor[j] = v;
    }
    if (j == 1) cursor[0] = 0;
}

__global__ void csr_fill(const int* __restrict__ ei, int* __restrict__ cursor,
                         int* __restrict__ csr) {
    int e = blockIdx.x * blockDim.x + threadIdx.x;
    if (e >= NE) return;
    int dst = ei[NE + e];
    int pos = atomicAdd(&cursor[dst], 1);
    csr[pos] = ei[e];
}

// ---------------- HMMA GEMM: out_bf[r][c] = bf16( dinv[r] * sum_k xb[r][k]*WT[c][k] ) ----
// 256 threads = 8 warps; warp w computes rows [16w,16w+16) x all 128 cols.
// mma.sync.m16n8k16 row.col: A = X rows (row-major), B = WT rows (col-major K x N).
// smem padded stride 68 uints/row -> conflict-free fragment LDS.
#define XS_STRIDE 68
#define SM_U (128 * XS_STRIDE)

__device__ __forceinline__ void mma16816(float* d, uint a0, uint a1, uint a2, uint a3,
                                         uint b0, uint b1) {
    asm volatile(
        "mma.sync.aligned.m16n8k16.row.col.f32.bf16.bf16.f32 "
        "{%0,%1,%2,%3}, {%4,%5,%6,%7}, {%8,%9}, {%0,%1,%2,%3};"
        : "+f"(d[0]), "+f"(d[1]), "+f"(d[2]), "+f"(d[3])
        : "r"(a0), "r"(a1), "r"(a2), "r"(a3), "r"(b0), "r"(b1));
}

__global__ void __launch_bounds__(256, 3)
gemm_mma(const uint* __restrict__ xb, const __nv_bfloat16* __restrict__ wtb,
         const int* __restrict__ cnt, uint* __restrict__ out) {
    __shared__ uint xs[SM_U];   // X tile, 128 rows x 64 uints, stride 68
    __shared__ uint ws[SM_U];   // WT,     128 rows x 64 uints, stride 68

    const int t = threadIdx.x;
    const int row0 = blockIdx.x * 128;

    // cooperative load: 2048 uint4 chunks each for X and WT
    const uint4* x4 = reinterpret_cast<const uint4*>(xb);
    const uint4* w4 = reinterpret_cast<const uint4*>(wtb);
    #pragma unroll
    for (int c = t; c < 2048; c += 256) {
        int r = c >> 4, q = c & 15;
        uint4 v = make_uint4(0, 0, 0, 0);
        if (row0 + r < NN) v = x4[(size_t)(row0 + r) * 16 + q];
        *reinterpret_cast<uint4*>(&xs[r * XS_STRIDE + q * 4]) = v;
        *reinterpret_cast<uint4*>(&ws[r * XS_STRIDE + q * 4]) = w4[(size_t)r * 16 + q];
    }
    __syncthreads();

    const int w    = t >> 5;          // warp 0..7 -> rows 16w..16w+15
    const int lane = t & 31;
    const int grp  = lane >> 2;       // 0..7
    const int tid  = lane & 3;        // 0..3

    float d[16][4];
    #pragma unroll
    for (int nb = 0; nb < 16; nb++)
        #pragma unroll
        for (int q = 0; q < 4; q++) d[nb][q] = 0.f;

    const uint* xrow0 = &xs[(w * 16 + grp) * XS_STRIDE + tid];       // a0/a2 base
    const uint* xrow1 = xrow0 + 8 * XS_STRIDE;                       // a1/a3 base

    #pragma unroll
    for (int kb = 0; kb < 8; kb++) {
        uint a0 = xrow0[kb * 8];
        uint a1 = xrow1[kb * 8];
        uint a2 = xrow0[kb * 8 + 4];
        uint a3 = xrow1[kb * 8 + 4];
        #pragma unroll
        for (int nb = 0; nb < 16; nb++) {
            const uint* wrow = &ws[(nb * 8 + grp) * XS_STRIDE + kb * 8 + tid];
            uint b0 = wrow[0];
            uint b1 = wrow[4];
            mma16816(d[nb], a0, a1, a2, a3, b0, b1);
        }
    }

    // epilogue: scale by dinv, pack bf16, store
    int r0 = row0 + w * 16 + grp;
    int r1 = r0 + 8;
    float dv0 = (r0 < NN) ? rsqrtf((float)cnt[r0] + 2.0f) : 0.f;
    float dv1 = (r1 < NN) ? rsqrtf((float)cnt[r1] + 2.0f) : 0.f;
    #pragma unroll
    for (int nb = 0; nb < 16; nb++) {
        if (r0 < NN) out[(size_t)r0 * 64 + nb * 4 + tid] = pk_bf16x2(d[nb][0] * dv0, d[nb][1] * dv0);
        if (r1 < NN) out[(size_t)r1 * 64 + nb * 4 + tid] = pk_bf16x2(d[nb][2] * dv1, d[nb][3] * dv1);
    }
}

// ---------------- gather + combine: half-warp per edge, LDG.128, bf16 in/out ----------------
#define ACC8(v)                                              \
    acc[0] += __uint_as_float((v).x << 16);                  \
    acc[1] += __uint_as_float((v).x & 0xffff0000u);          \
    acc[2] += __uint_as_float((v).y << 16);                  \
    acc[3] += __uint_as_float((v).y & 0xffff0000u);          \
    acc[4] += __uint_as_float((v).z << 16);                  \
    acc[5] += __uint_as_float((v).z & 0xffff0000u);          \
    acc[6] += __uint_as_float((v).w << 16);                  \
    acc[7] += __uint_as_float((v).w & 0xffff0000u);

__global__ void gather_combine(const int* __restrict__ rowptr, const int* __restrict__ csr,
                               const uint* __restrict__ g, const float* __restrict__ dinv,
                               const float* __restrict__ bias, uint* __restrict__ out) {
    int n = (blockIdx.x * blockDim.x + threadIdx.x) >> 5;
    if (n >= NN) return;
    int lane = threadIdx.x & 31;
    int half = lane >> 4;
    int hl   = lane & 15;
    int start = rowptr[n];
    int end   = rowptr[n + 1];

    const uint4* g4 = reinterpret_cast<const uint4*>(g);

    float acc[8];
    #pragma unroll
    for (int i = 0; i < 8; i++) acc[i] = 0.f;

    for (int base = start; base < end; base += 32) {
        int m = min(32, end - base);
        int s = (lane < m) ? csr[base + lane] : 0;
        int mp = m & ~1;
        #pragma unroll 4
        for (int j = 0; j < mp; j += 2) {
            int src = __shfl_sync(0xffffffffu, s, j + half);
            uint4 v = g4[(size_t)src * 16 + hl];
            ACC8(v)
        }
        if (m & 1) {
            int src = __shfl_sync(0xffffffffu, s, m - 1);
            if (half == 0) {
                uint4 v = g4[(size_t)src * 16 + hl];
                ACC8(v)
            }
        }
    }

    #pragma unroll
    for (int i = 0; i < 8; i++)
        acc[i] += __shfl_xor_sync(0xffffffffu, acc[i], 16);

    if (half == 0) {
        float dv = dinv[n];
        uint4 sv = g4[(size_t)n * 16 + hl];
        float s0 = __uint_as_float(sv.x << 16), s1 = __uint_as_float(sv.x & 0xffff0000u);
        float s2 = __uint_as_float(sv.y << 16), s3 = __uint_as_float(sv.y & 0xffff0000u);
        float s4 = __uint_as_float(sv.z << 16), s5 = __uint_as_float(sv.z & 0xffff0000u);
        float s6 = __uint_as_float(sv.w << 16), s7 = __uint_as_float(sv.w & 0xffff0000u);
        const float4* b4 = reinterpret_cast<const float4*>(bias);
        float4 b0 = b4[hl * 2], b1 = b4[hl * 2 + 1];
        float r0 = fmaxf(dv * (acc[0] + 2.f * s0) + b0.x, 0.f);
        float r1 = fmaxf(dv * (acc[1] + 2.f * s1) + b0.y, 0.f);
        float r2 = fmaxf(dv * (acc[2] + 2.f * s2) + b0.z, 0.f);
        float r3 = fmaxf(dv * (acc[3] + 2.f * s3) + b0.w, 0.f);
        float r4 = fmaxf(dv * (acc[4] + 2.f * s4) + b1.x, 0.f);
        float r5 = fmaxf(dv * (acc[5] + 2.f * s5) + b1.y, 0.f);
        float r6 = fmaxf(dv * (acc[6] + 2.f * s6) + b1.z, 0.f);
        float r7 = fmaxf(dv * (acc[7] + 2.f * s7) + b1.w, 0.f);
        reinterpret_cast<uint4*>(out)[(size_t)n * 16 + hl] =
            make_uint4(pk_bf16x2(r0, r1), pk_bf16x2(r2, r3),
                       pk_bf16x2(r4, r5), pk_bf16x2(r6, r7));
    }
}

// ---------------- pooling (bf16 x) ----------------
__global__ void pool_kernel(const uint* __restrict__ x, const int* __restrict__ batch,
                            float* __restrict__ gsum) {
    int f  = threadIdx.x;
    int n0 = blockIdx.x * 64;
    if (n0 >= NN) return;
    int nend = min(n0 + 64, NN);
    int cur = batch[n0];
    float acc = 0.f;
    for (int n = n0; n < nend; n++) {
        int b = batch[n];
        if (b != cur) { atomicAdd(&gsum[cur * F + f], acc); acc = 0.f; cur = b; }
        uint v = x[(size_t)n * 64 + (f >> 1)];
        acc += __uint_as_float((f & 1) ? (v & 0xffff0000u) : (v << 16));
    }
    atomicAdd(&gsum[cur * F + f], acc);
}

__global__ void cnt_kernel(const int* __restrict__ batch, float* __restrict__ gcnt) {
    int n = blockIdx.x * blockDim.x + threadIdx.x;
    if (n < NN) atomicAdd(&gcnt[batch[n]], 1.0f);
}

// ---------------- MLP head: one block per graph ----------------
__global__ void head_kernel(const float* __restrict__ gsum, const float* __restrict__ gcnt,
                            const float* __restrict__ fc1w, const float* __restrict__ fc1b,
                            const float* __restrict__ fc2w, const float* __restrict__ fc2b,
                            float* __restrict__ out) {
    int gI = blockIdx.x;
    int f  = threadIdx.x;
    __shared__ float pooled[F];
    __shared__ float red[F];
    float cnt = fmaxf(gcnt[gI], 1.0f);
    pooled[f] = gsum[gI * F + f] / cnt;
    __syncthreads();
    float a = fc1b[f];
    #pragma unroll 8
    for (int k = 0; k < F; k++) a += pooled[k] * fc1w[k * F + f];
    red[f] = fmaxf(a, 0.f) * fc2w[f];
    __syncthreads();
    #pragma unroll
    for (int s = 64; s > 0; s >>= 1) {
        if (f < s) red[f] += red[f + s];
        __syncthreads();
    }
    if (f == 0) out[gI] = red[0] + fc2b[0];
}

// ---------------- launch ----------------
extern "C" void kernel_launch(void* const* d_in, const int* in_sizes, int n_in,
                              void* d_out, int out_size) {
    const float* x      = (const float*)d_in[0];
    const int*   ei     = (const int*)d_in[1];
    const int*   batch  = (const int*)d_in[2];
    const float* conv_w = (const float*)d_in[4];
    const float* conv_b = (const float*)d_in[5];
    const float* fc1w   = (const float*)d_in[6];
    const float* fc1b   = (const float*)d_in[7];
    const float* fc2w   = (const float*)d_in[8];
    const float* fc2b   = (const float*)d_in[9];
    float* out = (float*)d_out;

    float *dinv, *gsum, *gcnt;
    uint *xb, *bufA;
    __nv_bfloat16* wtb;
    int *cnt, *rowptr, *cursor, *csr, *blksum, *blkoff;
    cudaGetSymbolAddress((void**)&xb,     g_xb);
    cudaGetSymbolAddress((void**)&bufA,   g_bufA);
    cudaGetSymbolAddress((void**)&wtb,    g_wtb);
    cudaGetSymbolAddress((void**)&cnt,    g_cnt);
    cudaGetSymbolAddress((void**)&rowptr, g_rowptr);
    cudaGetSymbolAddress((void**)&cursor, g_cursor);
    cudaGetSymbolAddress((void**)&csr,    g_csr);
    cudaGetSymbolAddress((void**)&blksum, g_blksum);
    cudaGetSymbolAddress((void**)&blkoff, g_blkoff);
    cudaGetSymbolAddress((void**)&dinv,   g_dinv);
    cudaGetSymbolAddress((void**)&gsum,   g_gsum);
    cudaGetSymbolAddress((void**)&gcnt,   g_gcnt);

    const int NB_SCAN = (NN + 1023) / 1024;   // 98
    const int GEMM_GRID = (NN + 127) / 128;   // 782
    const int CONV_N = NN * (F / 2) + NCONV * F * F;

    // gemm L0 at absolute launch #4 (the slot ncu captures); it needs only cnt + converts.
    fill_zero<<<(NN / 4 + 255) / 256, 256>>>((float*)cnt, NN / 4);            // 1
    count_kernel<<<(NE + 255) / 256, 256>>>(ei, cnt);                         // 2
    convert_all<<<(CONV_N + 255) / 256, 256>>>(x, conv_w, xb, wtb);           // 3
    gemm_mma<<<GEMM_GRID, 256>>>(xb, wtb, cnt, bufA);                         // 4 (profiled)
    scan1<<<NB_SCAN, 1024>>>(cnt, rowptr, blksum, dinv);                      // 5
    scan2<<<1, 128>>>(blksum, blkoff, NB_SCAN);                               // 6
    scan3<<<(NN + 255) / 256, 256>>>(rowptr, blkoff, cursor);                 // 7
    csr_fill<<<(NE + 255) / 256, 256>>>(ei, cursor, csr);                     // 8
    gather_combine<<<(NN * 32 + 255) / 256, 256>>>(rowptr, csr, bufA, dinv, conv_b, xb); // 9

    for (int l = 1; l < NCONV; l++) {
        gemm_mma<<<GEMM_GRID, 256>>>(xb, wtb + (size_t)l * F * F, cnt, bufA);
        gather_combine<<<(NN * 32 + 255) / 256, 256>>>(rowptr, csr, bufA, dinv,
                                                       conv_b + (size_t)l * F, xb);
    }

    // global mean pool
    fill_zero<<<(NG * F / 4 + 255) / 256, 256>>>(gsum, NG * F / 4);
    fill_zero<<<1, 128>>>(gcnt, NG / 4);
    pool_kernel<<<(NN + 63) / 64, 128>>>(xb, batch, gsum);
    cnt_kernel<<<(NN + 255) / 256, 256>>>(batch, gcnt);

    // head
    head_kernel<<<NG, 128>>>(gsum, gcnt, fc1w, fc1b, fc2w, fc2b, out);
}